// round 1
// baseline (speedup 1.0000x reference)
#include <cuda_runtime.h>
#include <cstdint>
#include <math.h>

#define T_LEN 2048
#define HID   2048
#define QKVT  8192
#define VTOT  4096
#define NHV   32
#define NHK   16

// ---------------- scratch (device globals; no allocation allowed) ----------------
__device__ float g_mixed[16777216];   // [T, 8192]  qkv-proj out
__device__ float g_conv [16777216];   // [T, 8192]  conv+silu out (q,k normalized in place)
__device__ float g_z    [ 8388608];   // [T, 4096]
__device__ float g_o    [ 8388608];   // [T, 32, 128] recurrence out -> gated-normed in place
__device__ float g_eg   [T_LEN*NHV];
__device__ float g_beta [T_LEN*NHV];

// ---------------- helpers ----------------
__device__ __forceinline__ float tf32r(float x){
    uint32_t u; asm("cvt.rna.tf32.f32 %0, %1;" : "=r"(u) : "f"(x));
    return __uint_as_float(u);
}
__device__ __forceinline__ void mma_tf32(float* c, const uint32_t* a, const uint32_t* b){
    asm volatile("mma.sync.aligned.m16n8k8.row.col.f32.tf32.tf32.f32 "
        "{%0,%1,%2,%3}, {%4,%5,%6,%7}, {%8,%9}, {%0,%1,%2,%3};\n"
        : "+f"(c[0]), "+f"(c[1]), "+f"(c[2]), "+f"(c[3])
        : "r"(a[0]), "r"(a[1]), "r"(a[2]), "r"(a[3]), "r"(b[0]), "r"(b[1]));
}

// ---------------- GEMM: C[M,N] = A[M,K] * B[N,K]^T  (tf32 tensor cores) ----------------
// tiles: 128x128x32, 256 threads (8 warps, 4x2), warp tile 32x64
__global__ __launch_bounds__(256) void gemm_tf32(
    const float* __restrict__ A, const float* __restrict__ B, float* __restrict__ C,
    int M, int N, int K)
{
    __shared__ __align__(16) float As[128][36];
    __shared__ __align__(16) float Bs[128][36];
    const int tid  = threadIdx.x;
    const int wid  = tid >> 5, lane = tid & 31;
    const int wm   = wid & 3,  wn   = wid >> 2;
    const int gid  = lane >> 2, tig = lane & 3;
    const float* Ab = A + (size_t)blockIdx.y * 128 * K;
    const float* Bb = B + (size_t)blockIdx.x * 128 * K;

    float acc[2][8][4];
    #pragma unroll
    for (int i = 0; i < 2; i++)
        #pragma unroll
        for (int j = 0; j < 8; j++)
            #pragma unroll
            for (int r = 0; r < 4; r++) acc[i][j][r] = 0.f;

    for (int k0 = 0; k0 < K; k0 += 32) {
        #pragma unroll
        for (int j = 0; j < 4; j++) {
            int s   = tid + j * 256;          // 0..1023 float4 slots
            int row = s >> 3, c4 = (s & 7) << 2;
            float4 va = *(const float4*)(Ab + (size_t)row * K + k0 + c4);
            float4 vb = *(const float4*)(Bb + (size_t)row * K + k0 + c4);
            float4 ta = make_float4(tf32r(va.x), tf32r(va.y), tf32r(va.z), tf32r(va.w));
            float4 tb = make_float4(tf32r(vb.x), tf32r(vb.y), tf32r(vb.z), tf32r(vb.w));
            *(float4*)&As[row][c4] = ta;
            *(float4*)&Bs[row][c4] = tb;
        }
        __syncthreads();
        #pragma unroll
        for (int kk = 0; kk < 32; kk += 8) {
            uint32_t af[2][4], bf[8][2];
            #pragma unroll
            for (int mt = 0; mt < 2; mt++) {
                int r = wm * 32 + mt * 16 + gid;
                af[mt][0] = __float_as_uint(As[r    ][kk + tig    ]);
                af[mt][1] = __float_as_uint(As[r + 8][kk + tig    ]);
                af[mt][2] = __float_as_uint(As[r    ][kk + tig + 4]);
                af[mt][3] = __float_as_uint(As[r + 8][kk + tig + 4]);
            }
            #pragma unroll
            for (int nt = 0; nt < 8; nt++) {
                int rn = wn * 64 + nt * 8 + gid;
                bf[nt][0] = __float_as_uint(Bs[rn][kk + tig    ]);
                bf[nt][1] = __float_as_uint(Bs[rn][kk + tig + 4]);
            }
            #pragma unroll
            for (int mt = 0; mt < 2; mt++)
                #pragma unroll
                for (int nt = 0; nt < 8; nt++)
                    mma_tf32(acc[mt][nt], af[mt], bf[nt]);
        }
        __syncthreads();
    }
    const int mrow = blockIdx.y * 128 + wm * 32;
    const int ncol = blockIdx.x * 128 + wn * 64;
    #pragma unroll
    for (int mt = 0; mt < 2; mt++)
        #pragma unroll
        for (int nt = 0; nt < 8; nt++) {
            int r0 = mrow + mt * 16 + gid;
            int c0 = ncol + nt * 8 + tig * 2;
            *(float2*)&C[(size_t)r0      * N + c0] = make_float2(acc[mt][nt][0], acc[mt][nt][1]);
            *(float2*)&C[(size_t)(r0 + 8)* N + c0] = make_float2(acc[mt][nt][2], acc[mt][nt][3]);
        }
}

// ---------------- gating: a,b projections + fused gdn gating ----------------
// block handles 4 timesteps x all 32 heads; 256 threads (8 warps x 4 heads each)
__global__ __launch_bounds__(256) void gating_kernel(
    const float* __restrict__ H, const float* __restrict__ Wa, const float* __restrict__ Wb,
    const float* __restrict__ A_log, const float* __restrict__ dtb,
    float* __restrict__ eg, float* __restrict__ beta)
{
    __shared__ float hs[4][HID];
    const int t0 = blockIdx.x * 4;
    const int tid = threadIdx.x;
    for (int i = tid; i < 4 * HID; i += 256)
        hs[i >> 11][i & (HID - 1)] = H[(size_t)(t0 + (i >> 11)) * HID + (i & (HID - 1))];
    __syncthreads();
    const int wid = tid >> 5, lane = tid & 31;
    for (int hh = 0; hh < 4; hh++) {
        int h = wid * 4 + hh;
        float aa[4] = {0,0,0,0}, bb[4] = {0,0,0,0};
        for (int i = lane; i < HID; i += 32) {
            float wa = Wa[h * HID + i], wb = Wb[h * HID + i];
            #pragma unroll
            for (int tt = 0; tt < 4; tt++) {
                float x = hs[tt][i];
                aa[tt] += x * wa; bb[tt] += x * wb;
            }
        }
        #pragma unroll
        for (int off = 16; off; off >>= 1) {
            #pragma unroll
            for (int tt = 0; tt < 4; tt++) {
                aa[tt] += __shfl_xor_sync(0xffffffffu, aa[tt], off);
                bb[tt] += __shfl_xor_sync(0xffffffffu, bb[tt], off);
            }
        }
        if (lane < 4) {
            int tt = lane;
            float x  = aa[tt] + dtb[h];
            float sp = (x > 15.f) ? x : log1pf(expf(x));
            float g  = -expf(A_log[h]) * sp;
            eg  [(t0 + tt) * NHV + h] = expf(g);
            beta[(t0 + tt) * NHV + h] = 1.f / (1.f + expf(-bb[tt]));
        }
    }
}

// ---------------- depthwise causal conv (K=4) + SiLU ----------------
__global__ void conv_silu_kernel(const float* __restrict__ x, const float* __restrict__ w,
                                 float* __restrict__ y)
{
    int idx = blockIdx.x * 256 + threadIdx.x;
    if (idx >= T_LEN * QKVT) return;
    int t = idx >> 13, c = idx & (QKVT - 1);
    float4 wc = *(const float4*)(w + c * 4);
    float acc = x[idx] * wc.w;
    if (t >= 1) acc += x[idx -     QKVT] * wc.z;
    if (t >= 2) acc += x[idx - 2 * QKVT] * wc.y;
    if (t >= 3) acc += x[idx - 3 * QKVT] * wc.x;
    y[idx] = acc / (1.f + expf(-acc));
}

// ---------------- l2-norm of q,k heads (in place), q pre-scaled by 128^-0.5 ----------------
__global__ void l2norm_kernel(float* __restrict__ conv)
{
    int g = blockIdx.x * 8 + (threadIdx.x >> 5);   // over T*32 slots (16 q + 16 k heads)
    int lane = threadIdx.x & 31;
    int t = g >> 5, s = g & 31;
    float* p = conv + (size_t)t * QKVT + s * 128;
    float x0 = p[lane], x1 = p[lane + 32], x2 = p[lane + 64], x3 = p[lane + 96];
    float ss = x0*x0 + x1*x1 + x2*x2 + x3*x3;
    #pragma unroll
    for (int off = 16; off; off >>= 1) ss += __shfl_xor_sync(0xffffffffu, ss, off);
    float inv = rsqrtf(ss + 1e-6f);
    if (s < 16) inv *= 0.08838834764831843f;   // q * 128^-0.5
    p[lane] = x0*inv; p[lane+32] = x1*inv; p[lane+64] = x2*inv; p[lane+96] = x3*inv;
}

// ---------------- gated delta-rule recurrence ----------------
// grid 128: CTA = (head hv, Dv slice of 32). 128 threads: warp=k-group (32 rows), lane=v-col.
// Each thread owns S[32 k][1 v] in registers.
__global__ __launch_bounds__(128) void recurrence_kernel(
    const float* __restrict__ conv, const float* __restrict__ eg,
    const float* __restrict__ beta, float* __restrict__ o)
{
    const int hv    = blockIdx.x >> 2;
    const int vbase = (blockIdx.x & 3) * 32;
    const int kh    = hv >> 1;                 // GQA ratio 2
    const int tid   = threadIdx.x, wid = tid >> 5, lane = tid & 31;
    __shared__ __align__(16) float ksh[128];
    __shared__ __align__(16) float qsh[128];
    __shared__ float p1[4][32], p2[4][32];

    float S[32];
    #pragma unroll
    for (int i = 0; i < 32; i++) S[i] = 0.f;

    const float* qb = conv +        kh * 128;
    const float* kb = conv + 2048 + kh * 128;
    const float* vb = conv + 4096 + hv * 128 + vbase;

    float kr = kb[tid], qr = qb[tid], vr = vb[lane];
    float egr = eg[hv], br = beta[hv];

    for (int t = 0; t < T_LEN; t++) {
        ksh[tid] = kr; qsh[tid] = qr;
        float vcur = vr, egc = egr, bc = br;
        __syncthreads();
        if (t + 1 < T_LEN) {                     // prefetch next step
            size_t off = (size_t)(t + 1) * QKVT;
            kr = kb[off + tid]; qr = qb[off + tid]; vr = vb[off + lane];
            egr = eg[(t + 1) * NHV + hv]; br = beta[(t + 1) * NHV + hv];
        }
        const float4* k4 = (const float4*)(ksh + wid * 32);
        const float4* q4 = (const float4*)(qsh + wid * 32);
        // phase 1: decay + partial pred = sum_k k * (eg*S)
        float a0 = 0.f, a1 = 0.f, a2 = 0.f, a3 = 0.f;
        #pragma unroll
        for (int i = 0; i < 8; i++) {
            float4 kv = k4[i];
            S[4*i+0] *= egc; a0 += kv.x * S[4*i+0];
            S[4*i+1] *= egc; a1 += kv.y * S[4*i+1];
            S[4*i+2] *= egc; a2 += kv.z * S[4*i+2];
            S[4*i+3] *= egc; a3 += kv.w * S[4*i+3];
        }
        p1[wid][lane] = (a0 + a1) + (a2 + a3);
        __syncthreads();
        float pred  = p1[0][lane] + p1[1][lane] + p1[2][lane] + p1[3][lane];
        float delta = bc * (vcur - pred);
        // phase 2: S += k*delta ; o_part = sum_k q * S
        float o0 = 0.f, o1 = 0.f, o2 = 0.f, o3 = 0.f;
        #pragma unroll
        for (int i = 0; i < 8; i++) {
            float4 kv = k4[i], qv = q4[i];
            S[4*i+0] += kv.x * delta; o0 += qv.x * S[4*i+0];
            S[4*i+1] += kv.y * delta; o1 += qv.y * S[4*i+1];
            S[4*i+2] += kv.z * delta; o2 += qv.z * S[4*i+2];
            S[4*i+3] += kv.w * delta; o3 += qv.w * S[4*i+3];
        }
        p2[wid][lane] = (o0 + o1) + (o2 + o3);
        __syncthreads();
        if (wid == 0)
            o[(size_t)t * VTOT + hv * 128 + vbase + lane] =
                p2[0][lane] + p2[1][lane] + p2[2][lane] + p2[3][lane];
    }
}

// ---------------- gated RMSNorm * silu(z) (in place on o) ----------------
__global__ void gated_norm_kernel(float* __restrict__ o, const float* __restrict__ z,
                                  const float* __restrict__ nw)
{
    int g = blockIdx.x * 8 + (threadIdx.x >> 5);   // over T*32 (t,head) groups
    int lane = threadIdx.x & 31;
    size_t base = (size_t)g * 128;
    float x0 = o[base+lane], x1 = o[base+lane+32], x2 = o[base+lane+64], x3 = o[base+lane+96];
    float ss = x0*x0 + x1*x1 + x2*x2 + x3*x3;
    #pragma unroll
    for (int off = 16; off; off >>= 1) ss += __shfl_xor_sync(0xffffffffu, ss, off);
    float r = rsqrtf(ss * (1.f / 128.f) + 1e-6f);
    #pragma unroll
    for (int j = 0; j < 4; j++) {
        int d = lane + 32 * j;
        float x = (j == 0 ? x0 : j == 1 ? x1 : j == 2 ? x2 : x3);
        float zz = z[base + d];
        o[base + d] = x * r * nw[d] * (zz / (1.f + expf(-zz)));
    }
}

// ---------------- launch ----------------
extern "C" void kernel_launch(void* const* d_in, const int* in_sizes, int n_in,
                              void* d_out, int out_size)
{
    const float* H     = (const float*)d_in[0];
    const float* Wqkv  = (const float*)d_in[1];
    const float* Wz    = (const float*)d_in[2];
    const float* Wa    = (const float*)d_in[3];
    const float* Wb    = (const float*)d_in[4];
    const float* Wc    = (const float*)d_in[5];
    const float* Wo    = (const float*)d_in[6];
    const float* nw    = (const float*)d_in[7];
    const float* A_log = (const float*)d_in[8];
    const float* dtb   = (const float*)d_in[9];
    float* out = (float*)d_out;

    float *mixed, *conv, *z, *o, *eg, *beta;
    cudaGetSymbolAddress((void**)&mixed, g_mixed);
    cudaGetSymbolAddress((void**)&conv,  g_conv);
    cudaGetSymbolAddress((void**)&z,     g_z);
    cudaGetSymbolAddress((void**)&o,     g_o);
    cudaGetSymbolAddress((void**)&eg,    g_eg);
    cudaGetSymbolAddress((void**)&beta,  g_beta);

    gemm_tf32<<<dim3(QKVT / 128, T_LEN / 128), 256>>>(H, Wqkv, mixed, T_LEN, QKVT, HID);
    gemm_tf32<<<dim3(VTOT / 128, T_LEN / 128), 256>>>(H, Wz, z, T_LEN, VTOT, HID);
    gating_kernel<<<T_LEN / 4, 256>>>(H, Wa, Wb, A_log, dtb, eg, beta);
    conv_silu_kernel<<<(T_LEN * QKVT) / 256, 256>>>(mixed, Wc, conv);
    l2norm_kernel<<<T_LEN * 32 / 8, 256>>>(conv);
    recurrence_kernel<<<128, 128>>>(conv, eg, beta, o);
    gated_norm_kernel<<<T_LEN * 32 / 8, 256>>>(o, z, nw);
    gemm_tf32<<<dim3(HID / 128, T_LEN / 128), 256>>>(o, Wo, out, T_LEN, HID, VTOT);
}